// round 17
// baseline (speedup 1.0000x reference)
#include <cuda_runtime.h>
#include <cuda_fp16.h>
#include <cstdint>

#define Bb 4
#define Tt 2048
#define Dd 1024
#define Hh 16
#define HSs 64
#define Mm (Bb*Tt)   // 8192
#define NCH 32       // cum-scan chunks (64 rows each)

// ---------------- scratch (device globals: allocation-free) ----------------
__device__ __half g_yv16 [Mm*Dd];         // x @ Wc, [B*T][D] fp16
__device__ float  g_csum [Bb*NCH*Dd];     // per-chunk column sums
__device__ float  g_y    [Mm*Dd];
__device__ float  g_norm [Mm*Dd];
__device__ float  g_z    [Mm*Dd];
__device__ __half g_x16  [Mm*Dd];
__device__ __half g_nrm16[Mm*Dd];
__device__ __half g_h116 [Mm*Dd];
__device__ __half g_WvC  [Dd*Dd];         // Wv concat as [d][n'] fp16
__device__ __half g_WoT  [Dd*Dd];         // [n][k] fp16
__device__ __half g_WcT  [Dd*Dd];         // combined (Wv@Wo)^T as [n][d] fp16
__device__ __half g_W1T  [Dd*Dd];
__device__ __half g_W2T  [Dd*Dd];

// ---------------- helpers ----------------
__device__ __forceinline__ uint32_t smem_u32(const void* p) {
    uint32_t a;
    asm("{ .reg .u64 t; cvta.to.shared.u64 t, %1; cvt.u32.u64 %0, t; }" : "=r"(a) : "l"(p));
    return a;
}

__device__ __forceinline__ void mma_f16(float* c, const unsigned* a, const unsigned* b) {
    asm volatile(
        "mma.sync.aligned.m16n8k16.row.col.f32.f16.f16.f32 "
        "{%0,%1,%2,%3}, {%4,%5,%6,%7}, {%8,%9}, {%0,%1,%2,%3};\n"
        : "+f"(c[0]), "+f"(c[1]), "+f"(c[2]), "+f"(c[3])
        : "r"(a[0]), "r"(a[1]), "r"(a[2]), "r"(a[3]), "r"(b[0]), "r"(b[1]));
}

__device__ __forceinline__ void ldsm_x4(unsigned* d, uint32_t addr) {
    asm volatile("ldmatrix.sync.aligned.m8n8.x4.shared.b16 {%0,%1,%2,%3}, [%4];"
        : "=r"(d[0]), "=r"(d[1]), "=r"(d[2]), "=r"(d[3]) : "r"(addr));
}

// ---------------- conversion kernels ----------------
__global__ void cvt_half_k(const float* __restrict__ in, __half* __restrict__ out) {
    int idx = blockIdx.x * 256 + threadIdx.x;
    float4 v = ((const float4*)in)[idx];
    ((__half2*)out)[idx * 2 + 0] = __floats2half2_rn(v.x, v.y);
    ((__half2*)out)[idx * 2 + 1] = __floats2half2_rn(v.z, v.w);
}

// fused weight prep (z selects):
// z 0: WvC[d][n'] = Wv[h(n'),d,s(n')]  (convert only, no transpose)
// z 1,2,3: Wo/Wf1/Wf2 row-major [K,N] -> transposed [n][k] fp16
__global__ void wtr_all_k(
    const float* __restrict__ Wv, const float* __restrict__ Wo,
    const float* __restrict__ Wf1, const float* __restrict__ Wf2,
    __half* __restrict__ oVC, __half* __restrict__ oO,
    __half* __restrict__ o1, __half* __restrict__ o2)
{
    __shared__ float s[32][33];
    const int z = blockIdx.z;
    int bn = blockIdx.x * 32, bk = blockIdx.y * 32;
    int tx = threadIdx.x, ty = threadIdx.y;
    if (z == 0) {
        #pragma unroll
        for (int i = 0; i < 4; i++) {
            int k = bk + ty + i * 8, n = bn + tx;
            float v = Wv[(size_t)(n >> 6) * 65536 + (size_t)k * 64 + (n & 63)];
            oVC[(size_t)k * 1024 + n] = __float2half(v);
        }
        return;
    }
    const float* in = (z == 1) ? Wo : (z == 2) ? Wf1 : Wf2;
    __half* out     = (z == 1) ? oO : (z == 2) ? o1 : o2;
    #pragma unroll
    for (int i = 0; i < 4; i++) {
        int k = bk + ty + i * 8, n = bn + tx;
        s[ty + i * 8][tx] = in[(size_t)k * 1024 + n];
    }
    __syncthreads();
    #pragma unroll
    for (int i = 0; i < 4; i++) {
        int n = bn + ty + i * 8, k = bk + tx;
        out[(size_t)n * 1024 + k] = __float2half(s[tx][ty + i * 8]);
    }
}

// ---------------- causal cumulative mean (attention + output proj, fused) ----------------
__global__ void cumA_k(const __half* __restrict__ V, float* __restrict__ csum) {
    const int chunk = blockIdx.x, cg = blockIdx.y, b = blockIdx.z;
    const int col = cg * 512 + threadIdx.x * 2;
    const __half2* p = (const __half2*)(V + (((size_t)b * Tt + chunk * 64) * Dd + col));
    float sx = 0.f, sy = 0.f;
    #pragma unroll 8
    for (int i = 0; i < 64; i++) {
        float2 v = __half22float2(p[i * (Dd / 2)]);
        sx += v.x; sy += v.y;
    }
    float* cs = csum + ((size_t)b * NCH + chunk) * Dd + col;
    cs[0] = sx; cs[1] = sy;
}

__global__ void cumB_k(const __half* __restrict__ V, const float* __restrict__ csum,
                       const float* __restrict__ bo, const float* __restrict__ x,
                       float* __restrict__ y) {
    const int chunk = blockIdx.x, cg = blockIdx.y, b = blockIdx.z;
    const int col = cg * 512 + threadIdx.x * 2;
    float ax = 0.f, ay = 0.f;
    for (int c = 0; c < chunk; c++) {
        const float* cs = csum + ((size_t)b * NCH + c) * Dd + col;
        ax += cs[0]; ay += cs[1];
    }
    const float2 bo2 = *(const float2*)(bo + col);
    const size_t rowbase = ((size_t)b * Tt + chunk * 64) * Dd + col;
    const __half2* p = (const __half2*)(V + rowbase);
    const float*  xp = x + rowbase;
    float*        yp = y + rowbase;
    #pragma unroll 4
    for (int i = 0; i < 64; i++) {
        float2 v = __half22float2(p[i * (Dd / 2)]);
        ax += v.x; ay += v.y;
        float inv = 1.0f / (float)(chunk * 64 + i + 1);
        float2 xv = *(const float2*)(xp + (size_t)i * Dd);
        float2 ov = make_float2(ax * inv + bo2.x + xv.x, ay * inv + bo2.y + xv.y);
        *(float2*)(yp + (size_t)i * Dd) = ov;
    }
}

// ---------------- FP16 tensor-core GEMM: 128x128x64, 3-stage cp.async + ldmatrix ----------------
// A [m][k] fp16, B [n][k] fp16. 16 k-iterations, 3 stages, wait_group 1 at top,
// prefetch kt+2 issued MID-COMPUTE (R8 lesson: front-loading the prefetch after
// the barrier collides with fragment loads). Pitch 72 halves: conflict-free.
// EPI 2: fp16 relu(+bias); EPI 3: fp32 +bias+add1+add2; EPI 4: fp16 plain.
#define PAH 72
#define ASZH (128*PAH)   // 9216 halves = 18432 B
#define BSZH (128*PAH)
#define NSTG 3
#define HGEMM_SMEM (NSTG*(ASZH + BSZH)*2)   // 110592 bytes

template<int EPI>
__global__ void __launch_bounds__(256, 2) hgemm_k(
    const __half* __restrict__ A, const __half* __restrict__ Bw, float* __restrict__ C,
    const float* __restrict__ bias, const float* __restrict__ add1,
    const float* __restrict__ add2,
    __half* __restrict__ Ch)
{
    extern __shared__ __half smh[];
    const uint32_t AsB = smem_u32(smh);
    const uint32_t BsB = AsB + NSTG * ASZH * 2;

    const int tid = threadIdx.x;
    const int lane = tid & 31, wid = tid >> 5;
    const int bn = blockIdx.x, bm = blockIdx.y;
    const int wm = (wid >> 2) * 64;
    const int wn = (wid & 3) * 32;
    const int q = lane >> 2, r = lane & 3;

    float acc[16][4];
    #pragma unroll
    for (int i = 0; i < 16; i++)
        #pragma unroll
        for (int j = 0; j < 4; j++) acc[i][j] = 0.f;

    const __half* a_src[4];
    const __half* b_src[4];
    uint32_t a_dst[4], b_dst[4];
    #pragma unroll
    for (int i = 0; i < 4; i++) {
        int f = tid + i * 256;
        int m_ = f >> 3, c_ = f & 7;
        a_src[i] = A  + (size_t)(bm * 128 + m_) * 1024 + c_ * 8;
        b_src[i] = Bw + (size_t)(bn * 128 + m_) * 1024 + c_ * 8;
        a_dst[i] = AsB + (uint32_t)(m_ * PAH + c_ * 8) * 2;
        b_dst[i] = BsB + (uint32_t)(m_ * PAH + c_ * 8) * 2;
    }

    const uint32_t aRow = (uint32_t)(wm + (lane & 7) + ((lane >> 3) & 1) * 8);
    const uint32_t aCol = (uint32_t)((lane >> 4) * 8);
    const uint32_t aBase = AsB + (aRow * PAH + aCol) * 2;
    const uint32_t bRow = (uint32_t)(wn + (lane & 7) + ((lane >> 4) & 1) * 8);
    const uint32_t bCol = (uint32_t)(((lane >> 3) & 1) * 8);
    const uint32_t bBase = BsB + (bRow * PAH + bCol) * 2;

#define CPA(kt, stg)                                                         \
    {                                                                        \
        _Pragma("unroll")                                                    \
        for (int i = 0; i < 4; i++) {                                        \
            asm volatile("cp.async.cg.shared.global [%0], [%1], 16;"         \
                :: "r"(a_dst[i] + (stg) * (uint32_t)(ASZH * 2)),             \
                   "l"(a_src[i] + (kt) * 64));                               \
            asm volatile("cp.async.cg.shared.global [%0], [%1], 16;"         \
                :: "r"(b_dst[i] + (stg) * (uint32_t)(BSZH * 2)),             \
                   "l"(b_src[i] + (kt) * 64));                               \
        }                                                                    \
        asm volatile("cp.async.commit_group;" ::: "memory");                 \
    }

#define COMPUTE_KS(stg, ks)                                                  \
    {                                                                        \
        unsigned afr[4][4], bfr[2][4];                                       \
        _Pragma("unroll")                                                    \
        for (int mt = 0; mt < 4; mt++)                                       \
            ldsm_x4(afr[mt], aBase + (stg) * (uint32_t)(ASZH * 2)            \
                             + (uint32_t)(mt * 16 * PAH * 2) + (ks) * 32);   \
        _Pragma("unroll")                                                    \
        for (int p = 0; p < 2; p++)                                          \
            ldsm_x4(bfr[p], bBase + (stg) * (uint32_t)(BSZH * 2)             \
                            + (uint32_t)(p * 16 * PAH * 2) + (ks) * 32);     \
        _Pragma("unroll")                                                    \
        for (int mt = 0; mt < 4; mt++)                                       \
            _Pragma("unroll")                                                \
            for (int nt = 0; nt < 4; nt++)                                   \
                mma_f16(acc[mt * 4 + nt], afr[mt], &bfr[nt >> 1][(nt & 1) * 2]); \
    }

    CPA(0, 0);
    CPA(1, 1);

    for (int kt = 0; kt < 16; kt++) {
        const int stg = kt % NSTG;
        if (kt == 15) { asm volatile("cp.async.wait_group 0;" ::: "memory"); }
        else          { asm volatile("cp.async.wait_group 1;" ::: "memory"); }
        __syncthreads();                 // tile kt visible; all warps done with stage (kt-1)%3
        COMPUTE_KS(stg, 0);
        COMPUTE_KS(stg, 1);
        if (kt < 14) CPA(kt + 2, (kt + 2) % NSTG);   // mid-compute prefetch (R8 lesson)
        COMPUTE_KS(stg, 2);
        COMPUTE_KS(stg, 3);
    }

    // ---- epilogue ----
    #pragma unroll
    for (int mt = 0; mt < 4; mt++) {
        #pragma unroll
        for (int half_ = 0; half_ < 2; half_++) {
            int m = bm * 128 + wm + mt * 16 + q + half_ * 8;
            #pragma unroll
            for (int nt = 0; nt < 4; nt++) {
                int n = bn * 128 + wn + nt * 8 + 2 * r;
                float v0 = acc[mt * 4 + nt][half_ * 2 + 0];
                float v1 = acc[mt * 4 + nt][half_ * 2 + 1];
                if (EPI == 2) {
                    float u0 = v0 + bias[n], u1 = v1 + bias[n + 1];
                    u0 = u0 > 0.f ? u0 : 0.f;
                    u1 = u1 > 0.f ? u1 : 0.f;
                    *(__half2*)(Ch + (size_t)m * Dd + n) = __floats2half2_rn(u0, u1);
                } else if (EPI == 3) {
                    size_t idx = (size_t)m * Dd + n;
                    float2 a1 = *(const float2*)(add1 + idx);
                    float2 a2 = *(const float2*)(add2 + idx);
                    float2 ov = make_float2(v0 + bias[n] + a1.x + a2.x,
                                            v1 + bias[n + 1] + a1.y + a2.y);
                    *(float2*)(C + idx) = ov;
                } else {   // EPI 4: plain fp16
                    *(__half2*)(Ch + (size_t)m * Dd + n) = __floats2half2_rn(v0, v1);
                }
            }
        }
    }
#undef CPA
#undef COMPUTE_KS
}

// ---------------- LayerNorm: one block per row; optional fp16 copy ----------------
__global__ void __launch_bounds__(256) ln_k(
    const float* __restrict__ in, const float* __restrict__ g,
    const float* __restrict__ bb, float* __restrict__ out,
    __half* __restrict__ out16)
{
    __shared__ float rs[8], rq[8];
    int row = blockIdx.x;
    const float4 v = ((const float4*)(in + (size_t)row * Dd))[threadIdx.x];
    float s = v.x + v.y + v.z + v.w;
    float q = v.x * v.x + v.y * v.y + v.z * v.z + v.w * v.w;
    #pragma unroll
    for (int w = 16; w >= 1; w >>= 1) {
        s += __shfl_xor_sync(0xffffffffu, s, w);
        q += __shfl_xor_sync(0xffffffffu, q, w);
    }
    int warp = threadIdx.x >> 5, lane = threadIdx.x & 31;
    if (lane == 0) { rs[warp] = s; rq[warp] = q; }
    __syncthreads();
    if (threadIdx.x == 0) {
        float ts = 0.f, tq = 0.f;
        #pragma unroll
        for (int i = 0; i < 8; i++) { ts += rs[i]; tq += rq[i]; }
        float mean = ts * (1.f / 1024.f);
        float var  = tq * (1.f / 1024.f) - mean * mean;
        rs[0] = mean;
        rq[0] = rsqrtf(var + 1e-5f);
    }
    __syncthreads();
    float mean = rs[0], inv = rq[0];
    const float4 g4 = ((const float4*)g )[threadIdx.x];
    const float4 b4 = ((const float4*)bb)[threadIdx.x];
    float4 ov;
    ov.x = (v.x - mean) * inv * g4.x + b4.x;
    ov.y = (v.y - mean) * inv * g4.y + b4.y;
    ov.z = (v.z - mean) * inv * g4.z + b4.z;
    ov.w = (v.w - mean) * inv * g4.w + b4.w;
    ((float4*)(out + (size_t)row * Dd))[threadIdx.x] = ov;
    if (out16) {
        ((__half2*)(out16 + (size_t)row * Dd))[threadIdx.x * 2 + 0] = __floats2half2_rn(ov.x, ov.y);
        ((__half2*)(out16 + (size_t)row * Dd))[threadIdx.x * 2 + 1] = __floats2half2_rn(ov.z, ov.w);
    }
}

// ---------------- driver ----------------
extern "C" void kernel_launch(void* const* d_in, const int* in_sizes, int n_in,
                              void* d_out, int out_size)
{
    const float* x   = (const float*)d_in[0];
    const float* Wk  = (const float*)d_in[1];   (void)Wk;  // unused: softmax uniform (scale=2^-30)
    const float* Wv  = (const float*)d_in[2];
    const float* Wo  = (const float*)d_in[3];
    const float* bo  = (const float*)d_in[4];
    const float* g1  = (const float*)d_in[5];
    const float* b1  = (const float*)d_in[6];
    const float* Wf1 = (const float*)d_in[7];
    const float* bf1 = (const float*)d_in[8];
    const float* Wf2 = (const float*)d_in[9];
    const float* bf2 = (const float*)d_in[10];
    const float* g2  = (const float*)d_in[11];
    const float* b2  = (const float*)d_in[12];
    float* out = (float*)d_out;

    float *py, *pnorm, *pz, *pcsum;
    __half *pyv16, *px16, *pnrm16, *ph116;
    __half *pWvC, *pWoT, *pWcT, *pW1T, *pW2T;
    cudaGetSymbolAddress((void**)&pyv16,  g_yv16);
    cudaGetSymbolAddress((void**)&pcsum,  g_csum);
    cudaGetSymbolAddress((void**)&py,     g_y);
    cudaGetSymbolAddress((void**)&pnorm,  g_norm);
    cudaGetSymbolAddress((void**)&pz,     g_z);
    cudaGetSymbolAddress((void**)&px16,   g_x16);
    cudaGetSymbolAddress((void**)&pnrm16, g_nrm16);
    cudaGetSymbolAddress((void**)&ph116,  g_h116);
    cudaGetSymbolAddress((void**)&pWvC,   g_WvC);
    cudaGetSymbolAddress((void**)&pWoT,   g_WoT);
    cudaGetSymbolAddress((void**)&pWcT,   g_WcT);
    cudaGetSymbolAddress((void**)&pW1T,   g_W1T);
    cudaGetSymbolAddress((void**)&pW2T,   g_W2T);

    cudaFuncSetAttribute(hgemm_k<2>, cudaFuncAttributeMaxDynamicSharedMemorySize, HGEMM_SMEM);
    cudaFuncSetAttribute(hgemm_k<3>, cudaFuncAttributeMaxDynamicSharedMemorySize, HGEMM_SMEM);
    cudaFuncSetAttribute(hgemm_k<4>, cudaFuncAttributeMaxDynamicSharedMemorySize, HGEMM_SMEM);

    dim3 gg(8, 64), tb(256);
    dim3 ggw(8, 8);
    dim3 tgrid(32, 32, 4), tblk(32, 8);
    dim3 cgrid(NCH, 2, 4);

    // 0: conversions (x -> fp16; weight prep, fused)
    cvt_half_k<<<Mm * Dd / 1024, 256>>>(x, px16);
    wtr_all_k<<<tgrid, tblk>>>(Wv, Wo, Wf1, Wf2, pWvC, pWoT, pW1T, pW2T);

    // 1: combined weight WcT[n][d] = (Wv_concat @ Wo)^T
    hgemm_k<4><<<ggw, tb, HGEMM_SMEM>>>(pWoT, pWvC, nullptr, nullptr, nullptr, nullptr, pWcT);

    // 2: yv = x @ Wc (fp16)
    hgemm_k<4><<<gg, tb, HGEMM_SMEM>>>(px16, pWcT, nullptr, nullptr, nullptr, nullptr, pyv16);

    // 3: y = cummean(yv) + bo + x
    cumA_k<<<cgrid, 256>>>(pyv16, pcsum);
    cumB_k<<<cgrid, 256>>>(pyv16, pcsum, bo, x, py);

    // 4: norm = LN1(y)  (+ fp16 copy)
    ln_k<<<Mm, 256>>>(py, g1, b1, pnorm, pnrm16);

    // 5: h1 = relu(norm @ Wf1 + bf1)  (fp16 output)
    hgemm_k<2><<<gg, tb, HGEMM_SMEM>>>(pnrm16, pW1T, nullptr, bf1, nullptr, nullptr, ph116);

    // 6: z = h1 @ Wf2 + bf2 + norm + x
    hgemm_k<3><<<gg, tb, HGEMM_SMEM>>>(ph116, pW2T, pz, bf2, pnorm, x, nullptr);

    // 7: out = LN2(z)
    ln_k<<<Mm, 256>>>(pz, g2, b2, out, nullptr);
}